// round 7
// baseline (speedup 1.0000x reference)
#include <cuda_runtime.h>
#include <cuda_bf16.h>

// ---------------------------------------------------------------------------
// BiRNN R7: RNN1 = 4 lanes/chain x 2 chains/thread (latency hidden by chain
// interleave), f32x2 row pairs, per-lane permuted weights, 2-stage shfl
// broadcast. RNN2 = smem broadcast + 4-way split accumulators.
// ---------------------------------------------------------------------------

typedef unsigned long long u64t;

__device__ float g_y[4096 * 18];  // concat(h_fwd, h_bwd) staging

static constexpr float SC = 2.8853900817779268f;  // 2 * log2(e)

__device__ __forceinline__ u64t pk2(float lo, float hi) {
    u64t r;
    asm("mov.b64 %0, {%1, %2};" : "=l"(r) : "f"(lo), "f"(hi));
    return r;
}
__device__ __forceinline__ void upk2(u64t v, float& lo, float& hi) {
    asm("mov.b64 {%0, %1}, %2;" : "=f"(lo), "=f"(hi) : "l"(v));
}
__device__ __forceinline__ u64t f2fma(u64t a, u64t b, u64t c) {
    u64t r;
    asm("fma.rn.f32x2 %0, %1, %2, %3;" : "=l"(r) : "l"(a), "l"(b), "l"(c));
    return r;
}
__device__ __forceinline__ u64t f2add(u64t a, u64t b) {
    u64t r;
    asm("add.rn.f32x2 %0, %1, %2;" : "=l"(r) : "l"(a), "l"(b));
    return r;
}
__device__ __forceinline__ float ex2f_(float x) {
    float r; asm("ex2.approx.f32 %0, %1;" : "=f"(r) : "f"(x)); return r;
}
__device__ __forceinline__ float rcpf_(float x) {
    float r; asm("rcp.approx.f32 %0, %1;" : "=f"(r) : "f"(x)); return r;
}
// s = 2*log2(e)*a ; tanh(a) = 1 - 2/(exp(2a)+1), exact identity, approx units
__device__ __forceinline__ float tanh_sc(float s) {
    float e = ex2f_(s);
    return fmaf(-2.0f, rcpf_(e + 1.0f), 1.0f);
}
__device__ __forceinline__ float getc(const float4& v, int m) {
    return m == 0 ? v.x : (m == 1 ? v.y : (m == 2 ? v.z : v.w));
}

// ---------------------------------------------------------------------------
// RNN1: lane r of 4 owns rows (2r, 2r+1) as one f32x2 pair; row 8 computed
// redundantly by all lanes. Each thread carries TWO same-direction chains.
// Local h slot k -> global column:
//   k0,k1 : 2r, 2r+1          (own, no shfl)
//   k2,k3 : 2(r^1), 2(r^1)+1  (stage-1 shfl_xor 1)
//   k4..k7: 2(r^2), 2(r^2)+1, 2(r^2^1), 2(r^2^1)+1   (stage-2 shfl_xor 2)
//   k8    : 8
// ---------------------------------------------------------------------------
template <bool BACK>
__device__ __forceinline__ void rnn1_body(
    int b0, int b1, int r, const float* __restrict__ x,
    const float* __restrict__ wih, const float* __restrict__ whh,
    const float* __restrict__ bih, const float* __restrict__ bhh, int T)
{
    const int row0 = 2 * r, row1 = 2 * r + 1;
    int cmap[9];
    cmap[0] = 2 * r;            cmap[1] = 2 * r + 1;
    cmap[2] = 2 * (r ^ 1);      cmap[3] = 2 * (r ^ 1) + 1;
    cmap[4] = 2 * (r ^ 2);      cmap[5] = 2 * (r ^ 2) + 1;
    cmap[6] = 2 * ((r ^ 2) ^ 1); cmap[7] = 2 * ((r ^ 2) ^ 1) + 1;
    cmap[8] = 8;

    // ---- weights (pre-scaled by SC), per-lane permuted columns
    u64t WH[9]; float W8[9];
#pragma unroll
    for (int k = 0; k < 9; k++) {
        int c = cmap[k];
        WH[k] = pk2(SC * __ldg(whh + row0 * 9 + c), SC * __ldg(whh + row1 * 9 + c));
        W8[k] = SC * __ldg(whh + 72 + c);
    }
    u64t WI[5]; float WI8[5];
#pragma unroll
    for (int d = 0; d < 5; d++) {
        WI[d] = pk2(SC * __ldg(wih + row0 * 5 + d), SC * __ldg(wih + row1 * 5 + d));
        WI8[d] = SC * __ldg(wih + 40 + d);
    }
    u64t BI = pk2(SC * (__ldg(bih + row0) + __ldg(bhh + row0)),
                  SC * (__ldg(bih + row1) + __ldg(bhh + row1)));
    float B8 = SC * (__ldg(bih + 8) + __ldg(bhh + 8));

    // ---- state, two chains
    float vs[2][9];
    u64t  vb[2][9];
#pragma unroll
    for (int c = 0; c < 2; c++)
#pragma unroll
        for (int i = 0; i < 9; i++) { vs[c][i] = 0.0f; vb[c][i] = 0ULL; }

    const int G = T >> 2;  // 4 steps/group = 20 floats = 5 float4
    const float4* xp0 = reinterpret_cast<const float4*>(x) + (size_t)b0 * ((size_t)T * 5 / 4);
    const float4* xp1 = reinterpret_cast<const float4*>(x) + (size_t)b1 * ((size_t)T * 5 / 4);

    float4 bA[2][5], bB[2][5];

    auto LOADG = [&](float4 (&buf)[2][5], int g) {
        int base = BACK ? 5 * (G - 1 - g) : 5 * g;
#pragma unroll
        for (int k = 0; k < 5; k++) {
            buf[0][k] = __ldg(xp0 + base + k);
            buf[1][k] = __ldg(xp1 + base + k);
        }
    };

    auto STEP = [&](int c, const float4 (&bf)[5], int off) {
        u64t ax = BI, ah = 0ULL;
        float a8x = B8, a8y = 0.0f;
        // x-contribution (independent of h, off the critical path)
#pragma unroll
        for (int d = 0; d < 5; d++) {
            int idx = off + d;
            float xv = getc(bf[idx >> 2], idx & 3);
            u64t xb = pk2(xv, xv);
            ax = f2fma(WI[d], xb, ax);
            a8x = fmaf(WI8[d], xv, a8x);
        }
        // h-contribution, split into two partials to halve chain latency
#pragma unroll
        for (int k = 0; k < 5; k++) {
            ax = f2fma(WH[k], vb[c][k], ax);
            a8x = fmaf(W8[k], vs[c][k], a8x);
        }
#pragma unroll
        for (int k = 5; k < 9; k++) {
            ah = f2fma(WH[k], vb[c][k], ah);
            a8y = fmaf(W8[k], vs[c][k], a8y);
        }
        u64t a = f2add(ax, ah);
        float a8 = a8x + a8y;
        float s0, s1;
        upk2(a, s0, s1);
        float o0 = tanh_sc(s0), o1 = tanh_sc(s1), o8 = tanh_sc(a8);
        // 2-stage butterfly broadcast of the 8 split rows
        float r0 = __shfl_xor_sync(0xffffffffu, o0, 1);
        float r1 = __shfl_xor_sync(0xffffffffu, o1, 1);
        float q0 = __shfl_xor_sync(0xffffffffu, o0, 2);
        float q1 = __shfl_xor_sync(0xffffffffu, o1, 2);
        float q2 = __shfl_xor_sync(0xffffffffu, r0, 2);
        float q3 = __shfl_xor_sync(0xffffffffu, r1, 2);
        vs[c][0] = o0; vs[c][1] = o1; vs[c][2] = r0; vs[c][3] = r1;
        vs[c][4] = q0; vs[c][5] = q1; vs[c][6] = q2; vs[c][7] = q3;
        vs[c][8] = o8;
#pragma unroll
        for (int i = 0; i < 9; i++) vb[c][i] = pk2(vs[c][i], vs[c][i]);
    };

    LOADG(bA, 0);
    for (int g = 0; g < G; g += 2) {
        if (g + 1 < G) LOADG(bB, g + 1);
#pragma unroll
        for (int s = 0; s < 4; s++) {
            int off = (BACK ? (3 - s) : s) * 5;
            STEP(0, bA[0], off);
            STEP(1, bA[1], off);
        }
        if (g + 2 < G) LOADG(bA, g + 2);
#pragma unroll
        for (int s = 0; s < 4; s++) {
            int off = (BACK ? (3 - s) : s) * 5;
            STEP(0, bB[0], off);
            STEP(1, bB[1], off);
        }
    }

    // writeback: own rows + row 8 (identical on all lanes -> benign dup store)
    int doff = BACK ? 9 : 0;
    float* d0 = g_y + (size_t)b0 * 18 + doff;
    float* d1 = g_y + (size_t)b1 * 18 + doff;
    d0[row0] = vs[0][0]; d0[row1] = vs[0][1]; d0[8] = vs[0][8];
    d1[row0] = vs[1][0]; d1[row1] = vs[1][1]; d1[8] = vs[1][8];
}

__global__ void __launch_bounds__(128, 1) rnn1_kernel(
    const float* __restrict__ x,
    const float* __restrict__ wih_f, const float* __restrict__ whh_f,
    const float* __restrict__ bih_f, const float* __restrict__ bhh_f,
    const float* __restrict__ wih_b, const float* __restrict__ whh_b,
    const float* __restrict__ bih_b, const float* __restrict__ bhh_b,
    int T, int B)
{
    int gtid = blockIdx.x * blockDim.x + threadIdx.x;
    int r    = gtid & 3;
    int slot = gtid >> 2;          // [0, B) ; first half fwd, second half bwd
    int hB   = B >> 1;             // 2048
    if (slot < hB) {
        rnn1_body<false>(slot, slot + hB, r, x, wih_f, whh_f, bih_f, bhh_f, T);
    } else {
        int s = slot - hB;
        rnn1_body<true>(s, s + hB, r, x, wih_b, whh_b, bih_b, bhh_b, T);
    }
}

// ---------------------------------------------------------------------------
// RNN2 + projection: warp per batch, smem h-broadcast, 4-way split accums.
// ---------------------------------------------------------------------------
#define ROWF 36  // padded row stride (floats): 16B-aligned, conflict-free

__global__ void __launch_bounds__(128) rnn2_kernel(
    const float* __restrict__ wih2, const float* __restrict__ whh2,
    const float* __restrict__ bih2, const float* __restrict__ bhh2,
    const float* __restrict__ wout, const float* __restrict__ bout,
    float* __restrict__ out, int B)
{
    __shared__ __align__(16) float hbuf[4][25 * ROWF];
    __shared__ float wsm[96];

    int tid = threadIdx.x;
    int wid = tid >> 5;
    int lane = tid & 31;
    int b = blockIdx.x * 4 + wid;

    if (tid < 96) wsm[tid] = __ldg(wout + tid);
    __syncthreads();
    if (b >= B) return;

    // whh2 row for this lane: 32 floats = 8 x float4 (128B aligned)
    float WHR[32];
    {
        const float4* wr = reinterpret_cast<const float4*>(whh2 + lane * 32);
#pragma unroll
        for (int q = 0; q < 8; q++) {
            float4 v = __ldg(wr + q);
            WHR[4 * q + 0] = SC * v.x; WHR[4 * q + 1] = SC * v.y;
            WHR[4 * q + 2] = SC * v.z; WHR[4 * q + 3] = SC * v.w;
        }
    }
    float bi = SC * (__ldg(bih2 + lane) + __ldg(bhh2 + lane));

    // step 0: input y from g_y, two partial chains
    const float* yb = g_y + (size_t)b * 18;
    float ac0 = bi, ac1 = 0.0f;
#pragma unroll
    for (int j = 0; j < 9; j++)
        ac0 = fmaf(SC * __ldg(wih2 + lane * 18 + j), __ldg(yb + j), ac0);
#pragma unroll
    for (int j = 9; j < 18; j++)
        ac1 = fmaf(SC * __ldg(wih2 + lane * 18 + j), __ldg(yb + j), ac1);
    float h = tanh_sc(ac0 + ac1);

    float* hr = hbuf[wid];
    hr[lane] = h;
    __syncwarp();

#pragma unroll 1
    for (int t = 1; t < 25; t++) {
        const float4* rp = reinterpret_cast<const float4*>(hr + (t - 1) * ROWF);
        float p0 = bi, p1 = 0.0f, p2 = 0.0f, p3 = 0.0f;
#pragma unroll
        for (int q = 0; q < 8; q++) {
            float4 v = rp[q];
            float* pp = (q < 2) ? &p0 : ((q < 4) ? &p1 : ((q < 6) ? &p2 : &p3));
            *pp = fmaf(WHR[4 * q + 0], v.x, *pp);
            *pp = fmaf(WHR[4 * q + 1], v.y, *pp);
            *pp = fmaf(WHR[4 * q + 2], v.z, *pp);
            *pp = fmaf(WHR[4 * q + 3], v.w, *pp);
        }
        h = tanh_sc((p0 + p1) + (p2 + p3));
        hr[t * ROWF + lane] = h;
        __syncwarp();
    }

    // epilogue: 75 outputs -> lanes (idx = lane, lane+32, lane+64)
    float bo0 = __ldg(bout + 0), bo1 = __ldg(bout + 1), bo2 = __ldg(bout + 2);
    float* ob = out + (size_t)b * 75;
#pragma unroll
    for (int k = 0; k < 3; k++) {
        int idx = lane + 32 * k;
        if (idx < 75) {
            int t = idx / 3;
            int o = idx - 3 * t;
            const float4* rp = reinterpret_cast<const float4*>(hr + t * ROWF);
            float p0 = (o == 0) ? bo0 : ((o == 1) ? bo1 : bo2);
            float p1 = 0.0f, p2 = 0.0f, p3 = 0.0f;
#pragma unroll
            for (int q = 0; q < 8; q++) {
                float4 v = rp[q];
                float* pp = (q < 2) ? &p0 : ((q < 4) ? &p1 : ((q < 6) ? &p2 : &p3));
                *pp = fmaf(wsm[o * 32 + 4 * q + 0], v.x, *pp);
                *pp = fmaf(wsm[o * 32 + 4 * q + 1], v.y, *pp);
                *pp = fmaf(wsm[o * 32 + 4 * q + 2], v.z, *pp);
                *pp = fmaf(wsm[o * 32 + 4 * q + 3], v.w, *pp);
            }
            ob[idx] = (p0 + p1) + (p2 + p3);
        }
    }
}

// ---------------------------------------------------------------------------
extern "C" void kernel_launch(void* const* d_in, const int* in_sizes, int n_in,
                              void* d_out, int out_size)
{
    const float* x      = (const float*)d_in[0];
    const float* wih_f  = (const float*)d_in[1];
    const float* whh_f  = (const float*)d_in[2];
    const float* bih_f  = (const float*)d_in[3];
    const float* bhh_f  = (const float*)d_in[4];
    const float* wih_b  = (const float*)d_in[5];
    const float* whh_b  = (const float*)d_in[6];
    const float* bih_b  = (const float*)d_in[7];
    const float* bhh_b  = (const float*)d_in[8];
    const float* wih2   = (const float*)d_in[9];
    const float* whh2   = (const float*)d_in[10];
    const float* bih2   = (const float*)d_in[11];
    const float* bhh2   = (const float*)d_in[12];
    const float* wout   = (const float*)d_in[13];
    const float* bout   = (const float*)d_in[14];
    float* out = (float*)d_out;

    int B = out_size / 75;                 // 4096
    int T = in_sizes[0] / (B * 5);         // 2048

    // 4 lanes/chain, 2 chains/thread: B slots * 4 lanes = 4*B threads
    int blocks1 = (4 * B) / 128;           // 128 blocks of 128
    rnn1_kernel<<<blocks1, 128>>>(x, wih_f, whh_f, bih_f, bhh_f,
                                  wih_b, whh_b, bih_b, bhh_b, T, B);

    rnn2_kernel<<<B / 4, 128>>>(wih2, whh2, bih2, bhh2, wout, bout, out, B);
}

// round 8
// speedup vs baseline: 1.6495x; 1.6495x over previous
#include <cuda_runtime.h>
#include <cuda_bf16.h>

// ---------------------------------------------------------------------------
// BiRNN R8: RNN1 = 4 lanes/chain, 1 chain/thread, 1024 warps in 128 blocks of
// 256 threads -> exactly 2 warps per SMSP (pipe overlap, no solo-warp Sum(rt)
// pace). f32x2 row pairs, per-lane permuted weights, 2-stage shfl broadcast,
// redundant row8 (keeps SIMT uniform). RNN2 = smem broadcast (unchanged).
// ---------------------------------------------------------------------------

typedef unsigned long long u64t;

__device__ float g_y[4096 * 18];  // concat(h_fwd, h_bwd) staging

static constexpr float SC = 2.8853900817779268f;  // 2 * log2(e)

__device__ __forceinline__ u64t pk2(float lo, float hi) {
    u64t r;
    asm("mov.b64 %0, {%1, %2};" : "=l"(r) : "f"(lo), "f"(hi));
    return r;
}
__device__ __forceinline__ void upk2(u64t v, float& lo, float& hi) {
    asm("mov.b64 {%0, %1}, %2;" : "=f"(lo), "=f"(hi) : "l"(v));
}
__device__ __forceinline__ u64t f2fma(u64t a, u64t b, u64t c) {
    u64t r;
    asm("fma.rn.f32x2 %0, %1, %2, %3;" : "=l"(r) : "l"(a), "l"(b), "l"(c));
    return r;
}
__device__ __forceinline__ u64t f2add(u64t a, u64t b) {
    u64t r;
    asm("add.rn.f32x2 %0, %1, %2;" : "=l"(r) : "l"(a), "l"(b));
    return r;
}
__device__ __forceinline__ float ex2f_(float x) {
    float r; asm("ex2.approx.f32 %0, %1;" : "=f"(r) : "f"(x)); return r;
}
__device__ __forceinline__ float rcpf_(float x) {
    float r; asm("rcp.approx.f32 %0, %1;" : "=f"(r) : "f"(x)); return r;
}
// s = 2*log2(e)*a ; tanh(a) = 1 - 2/(exp(2a)+1), exact identity, approx units
__device__ __forceinline__ float tanh_sc(float s) {
    float e = ex2f_(s);
    return fmaf(-2.0f, rcpf_(e + 1.0f), 1.0f);
}
__device__ __forceinline__ float getc(const float4& v, int m) {
    return m == 0 ? v.x : (m == 1 ? v.y : (m == 2 ? v.z : v.w));
}

// ---------------------------------------------------------------------------
// RNN1: lane r of 4 owns rows (2r, 2r+1) as one f32x2 pair; row 8 computed
// redundantly by all lanes (uniform stream). One chain per thread.
// Local h slot k -> global column:
//   k0,k1 : 2r, 2r+1           (own, no shfl)
//   k2,k3 : 2(r^1), 2(r^1)+1   (stage-1 shfl_xor 1)
//   k4..k7: 2(r^2), 2(r^2)+1, 2((r^2)^1), 2((r^2)^1)+1  (stage-2 shfl_xor 2)
//   k8    : 8
// ---------------------------------------------------------------------------
template <bool BACK>
__device__ __forceinline__ void rnn1_body(
    int b, int r, const float* __restrict__ x,
    const float* __restrict__ wih, const float* __restrict__ whh,
    const float* __restrict__ bih, const float* __restrict__ bhh, int T)
{
    const int row0 = 2 * r, row1 = 2 * r + 1;
    int cmap[9];
    cmap[0] = 2 * r;             cmap[1] = 2 * r + 1;
    cmap[2] = 2 * (r ^ 1);       cmap[3] = 2 * (r ^ 1) + 1;
    cmap[4] = 2 * (r ^ 2);       cmap[5] = 2 * (r ^ 2) + 1;
    cmap[6] = 2 * ((r ^ 2) ^ 1); cmap[7] = 2 * ((r ^ 2) ^ 1) + 1;
    cmap[8] = 8;

    // ---- weights (pre-scaled by SC), per-lane permuted columns
    u64t WH[9]; float W8[9];
#pragma unroll
    for (int k = 0; k < 9; k++) {
        int c = cmap[k];
        WH[k] = pk2(SC * __ldg(whh + row0 * 9 + c), SC * __ldg(whh + row1 * 9 + c));
        W8[k] = SC * __ldg(whh + 72 + c);
    }
    u64t WI[5]; float WI8[5];
#pragma unroll
    for (int d = 0; d < 5; d++) {
        WI[d] = pk2(SC * __ldg(wih + row0 * 5 + d), SC * __ldg(wih + row1 * 5 + d));
        WI8[d] = SC * __ldg(wih + 40 + d);
    }
    u64t BI = pk2(SC * (__ldg(bih + row0) + __ldg(bhh + row0)),
                  SC * (__ldg(bih + row1) + __ldg(bhh + row1)));
    float B8 = SC * (__ldg(bih + 8) + __ldg(bhh + 8));

    // ---- state
    float vs[9];
    u64t  vb[9];
#pragma unroll
    for (int i = 0; i < 9; i++) { vs[i] = 0.0f; vb[i] = 0ULL; }

    const int G = T >> 2;  // 4 steps/group = 20 floats = 5 float4
    const float4* xp = reinterpret_cast<const float4*>(x) + (size_t)b * ((size_t)T * 5 / 4);

    float4 bA[5], bB[5];

    auto LOADG = [&](float4 (&buf)[5], int g) {
        int base = BACK ? 5 * (G - 1 - g) : 5 * g;
#pragma unroll
        for (int k = 0; k < 5; k++) buf[k] = __ldg(xp + base + k);
    };

    auto STEP = [&](const float4 (&bf)[5], int off) {
        u64t ax = BI, ah = 0ULL;
        float a8x = B8, a8y = 0.0f;
        // x-contribution (independent of h, off the critical path)
#pragma unroll
        for (int d = 0; d < 5; d++) {
            int idx = off + d;
            float xv = getc(bf[idx >> 2], idx & 3);
            u64t xb = pk2(xv, xv);
            ax = f2fma(WI[d], xb, ax);
            a8x = fmaf(WI8[d], xv, a8x);
        }
        // h-contribution, two partials to halve chain latency
#pragma unroll
        for (int k = 0; k < 5; k++) {
            ax = f2fma(WH[k], vb[k], ax);
            a8x = fmaf(W8[k], vs[k], a8x);
        }
#pragma unroll
        for (int k = 5; k < 9; k++) {
            ah = f2fma(WH[k], vb[k], ah);
            a8y = fmaf(W8[k], vs[k], a8y);
        }
        u64t a = f2add(ax, ah);
        float a8 = a8x + a8y;
        float s0, s1;
        upk2(a, s0, s1);
        float o0 = tanh_sc(s0), o1 = tanh_sc(s1), o8 = tanh_sc(a8);
        // 2-stage butterfly broadcast of the 8 split rows
        float r0 = __shfl_xor_sync(0xffffffffu, o0, 1);
        float r1 = __shfl_xor_sync(0xffffffffu, o1, 1);
        float q0 = __shfl_xor_sync(0xffffffffu, o0, 2);
        float q1 = __shfl_xor_sync(0xffffffffu, o1, 2);
        float q2 = __shfl_xor_sync(0xffffffffu, r0, 2);
        float q3 = __shfl_xor_sync(0xffffffffu, r1, 2);
        vs[0] = o0; vs[1] = o1; vs[2] = r0; vs[3] = r1;
        vs[4] = q0; vs[5] = q1; vs[6] = q2; vs[7] = q3;
        vs[8] = o8;
#pragma unroll
        for (int i = 0; i < 9; i++) vb[i] = pk2(vs[i], vs[i]);
    };

    LOADG(bA, 0);
    for (int g = 0; g < G; g += 2) {
        if (g + 1 < G) LOADG(bB, g + 1);
#pragma unroll
        for (int s = 0; s < 4; s++) STEP(bA, (BACK ? (3 - s) : s) * 5);
        if (g + 2 < G) LOADG(bA, g + 2);
#pragma unroll
        for (int s = 0; s < 4; s++) STEP(bB, (BACK ? (3 - s) : s) * 5);
    }

    // writeback: own rows + row 8 (identical on all lanes -> benign dup store)
    float* dst = g_y + (size_t)b * 18 + (BACK ? 9 : 0);
    dst[row0] = vs[0]; dst[row1] = vs[1]; dst[8] = vs[8];
}

__global__ void __launch_bounds__(256, 1) rnn1_kernel(
    const float* __restrict__ x,
    const float* __restrict__ wih_f, const float* __restrict__ whh_f,
    const float* __restrict__ bih_f, const float* __restrict__ bhh_f,
    const float* __restrict__ wih_b, const float* __restrict__ whh_b,
    const float* __restrict__ bih_b, const float* __restrict__ bhh_b,
    int T, int B)
{
    int gtid = blockIdx.x * blockDim.x + threadIdx.x;
    int r     = gtid & 3;
    int chain = gtid >> 2;         // [0, 2B); first B fwd, second B bwd
    if (chain < B) {
        rnn1_body<false>(chain, r, x, wih_f, whh_f, bih_f, bhh_f, T);
    } else {
        rnn1_body<true>(chain - B, r, x, wih_b, whh_b, bih_b, bhh_b, T);
    }
}

// ---------------------------------------------------------------------------
// RNN2 + projection: warp per batch, smem h-broadcast, split accumulators.
// ---------------------------------------------------------------------------
#define ROWF 36  // padded row stride (floats): 16B-aligned, conflict-free

__global__ void __launch_bounds__(128) rnn2_kernel(
    const float* __restrict__ wih2, const float* __restrict__ whh2,
    const float* __restrict__ bih2, const float* __restrict__ bhh2,
    const float* __restrict__ wout, const float* __restrict__ bout,
    float* __restrict__ out, int B)
{
    __shared__ __align__(16) float hbuf[4][25 * ROWF];
    __shared__ float wsm[96];

    int tid = threadIdx.x;
    int wid = tid >> 5;
    int lane = tid & 31;
    int b = blockIdx.x * 4 + wid;

    if (tid < 96) wsm[tid] = __ldg(wout + tid);
    __syncthreads();
    if (b >= B) return;

    float WHR[32];
    {
        const float4* wr = reinterpret_cast<const float4*>(whh2 + lane * 32);
#pragma unroll
        for (int q = 0; q < 8; q++) {
            float4 v = __ldg(wr + q);
            WHR[4 * q + 0] = SC * v.x; WHR[4 * q + 1] = SC * v.y;
            WHR[4 * q + 2] = SC * v.z; WHR[4 * q + 3] = SC * v.w;
        }
    }
    float bi = SC * (__ldg(bih2 + lane) + __ldg(bhh2 + lane));

    // step 0: input y from g_y, two partial chains
    const float* yb = g_y + (size_t)b * 18;
    float ac0 = bi, ac1 = 0.0f;
#pragma unroll
    for (int j = 0; j < 9; j++)
        ac0 = fmaf(SC * __ldg(wih2 + lane * 18 + j), __ldg(yb + j), ac0);
#pragma unroll
    for (int j = 9; j < 18; j++)
        ac1 = fmaf(SC * __ldg(wih2 + lane * 18 + j), __ldg(yb + j), ac1);
    float h = tanh_sc(ac0 + ac1);

    float* hr = hbuf[wid];
    hr[lane] = h;
    __syncwarp();

#pragma unroll 1
    for (int t = 1; t < 25; t++) {
        const float4* rp = reinterpret_cast<const float4*>(hr + (t - 1) * ROWF);
        float p0 = bi, p1 = 0.0f, p2 = 0.0f, p3 = 0.0f;
#pragma unroll
        for (int q = 0; q < 8; q++) {
            float4 v = rp[q];
            float* pp = (q < 2) ? &p0 : ((q < 4) ? &p1 : ((q < 6) ? &p2 : &p3));
            *pp = fmaf(WHR[4 * q + 0], v.x, *pp);
            *pp = fmaf(WHR[4 * q + 1], v.y, *pp);
            *pp = fmaf(WHR[4 * q + 2], v.z, *pp);
            *pp = fmaf(WHR[4 * q + 3], v.w, *pp);
        }
        h = tanh_sc((p0 + p1) + (p2 + p3));
        hr[t * ROWF + lane] = h;
        __syncwarp();
    }

    // epilogue: 75 outputs -> lanes (idx = lane, lane+32, lane+64)
    float bo0 = __ldg(bout + 0), bo1 = __ldg(bout + 1), bo2 = __ldg(bout + 2);
    float* ob = out + (size_t)b * 75;
#pragma unroll
    for (int k = 0; k < 3; k++) {
        int idx = lane + 32 * k;
        if (idx < 75) {
            int t = idx / 3;
            int o = idx - 3 * t;
            const float4* rp = reinterpret_cast<const float4*>(hr + t * ROWF);
            float p0 = (o == 0) ? bo0 : ((o == 1) ? bo1 : bo2);
            float p1 = 0.0f, p2 = 0.0f, p3 = 0.0f;
#pragma unroll
            for (int q = 0; q < 8; q++) {
                float4 v = rp[q];
                float* pp = (q < 2) ? &p0 : ((q < 4) ? &p1 : ((q < 6) ? &p2 : &p3));
                *pp = fmaf(wsm[o * 32 + 4 * q + 0], v.x, *pp);
                *pp = fmaf(wsm[o * 32 + 4 * q + 1], v.y, *pp);
                *pp = fmaf(wsm[o * 32 + 4 * q + 2], v.z, *pp);
                *pp = fmaf(wsm[o * 32 + 4 * q + 3], v.w, *pp);
            }
            ob[idx] = (p0 + p1) + (p2 + p3);
        }
    }
}

// ---------------------------------------------------------------------------
extern "C" void kernel_launch(void* const* d_in, const int* in_sizes, int n_in,
                              void* d_out, int out_size)
{
    const float* x      = (const float*)d_in[0];
    const float* wih_f  = (const float*)d_in[1];
    const float* whh_f  = (const float*)d_in[2];
    const float* bih_f  = (const float*)d_in[3];
    const float* bhh_f  = (const float*)d_in[4];
    const float* wih_b  = (const float*)d_in[5];
    const float* whh_b  = (const float*)d_in[6];
    const float* bih_b  = (const float*)d_in[7];
    const float* bhh_b  = (const float*)d_in[8];
    const float* wih2   = (const float*)d_in[9];
    const float* whh2   = (const float*)d_in[10];
    const float* bih2   = (const float*)d_in[11];
    const float* bhh2   = (const float*)d_in[12];
    const float* wout   = (const float*)d_in[13];
    const float* bout   = (const float*)d_in[14];
    float* out = (float*)d_out;

    int B = out_size / 75;                 // 4096
    int T = in_sizes[0] / (B * 5);         // 2048

    // 4 lanes/chain, 1 chain/thread: 2B chains * 4 = 8*B threads.
    // Blocks of 256 -> 128 blocks -> 1 block/SM -> 2 warps per SMSP.
    int blocks1 = (8 * B) / 256;           // 128
    rnn1_kernel<<<blocks1, 256>>>(x, wih_f, whh_f, bih_f, bhh_f,
                                  wih_b, whh_b, bih_b, bhh_b, T, B);

    rnn2_kernel<<<B / 4, 128>>>(wih2, whh2, bih2, bhh2, wout, bout, out, B);
}